// round 10
// baseline (speedup 1.0000x reference)
#include <cuda_runtime.h>
#include <cuda_bf16.h>
#include <math.h>

// ---------------------------------------------------------------------------
// Problem constants
// ---------------------------------------------------------------------------
#define TSEQ 2048
#define HD   512        // hidden size H
#define EMB  512        // embedding dim E
#define G4H  2048       // 4*H
#define NTAGS 12
#define START_TAG 10
#define STOP_TAG  11
#define NEGV (-10000.0f)

// ---------------------------------------------------------------------------
// Scratch (device globals; no allocations allowed)
// ---------------------------------------------------------------------------
__device__ float g_x0[TSEQ * EMB];                 // embedded input      4 MB
__device__ float g_G[2 * TSEQ * G4H];              // input projections  32 MB (reused per layer)
__device__ float g_hcat0[TSEQ * 2 * HD];           // layer0 output       8 MB
__device__ float g_hcat1[TSEQ * 2 * HD];           // layer1 output       8 MB
__device__ float g_feats[TSEQ * NTAGS];
__device__ unsigned long long g_hstamp[2 * 2 * HD]; // [dir][parity][H] stamped h

// ---------------------------------------------------------------------------
// Helpers
// ---------------------------------------------------------------------------
__device__ __forceinline__ unsigned long long ld_relaxed_u64(const unsigned long long* p) {
    unsigned long long v;
    asm volatile("ld.relaxed.gpu.global.b64 %0, [%1];" : "=l"(v) : "l"(p) : "memory");
    return v;
}
__device__ __forceinline__ void st_relaxed_u64(unsigned long long* p, unsigned long long v) {
    asm volatile("st.relaxed.gpu.global.b64 [%0], %1;" :: "l"(p), "l"(v) : "memory");
}

// packed f32x2 FMA (FFMA2 — only reachable via PTX)
__device__ __forceinline__ unsigned long long ffma2(unsigned long long a,
                                                    unsigned long long b,
                                                    unsigned long long c) {
    unsigned long long d;
    asm("fma.rn.f32x2 %0, %1, %2, %3;" : "=l"(d) : "l"(a), "l"(b), "l"(c));
    return d;
}
__device__ __forceinline__ float2 unpack2(unsigned long long v) {
    float2 r;
    asm("mov.b64 {%0, %1}, %2;" : "=f"(r.x), "=f"(r.y) : "l"(v));
    return r;
}

// HW tanh (MUFU-class, ~1e-5 abs err) and sigmoid via tanh
__device__ __forceinline__ float tanh_hw(float x) {
    float y;
    asm("tanh.approx.f32 %0, %1;" : "=f"(y) : "f"(x));
    return y;
}
__device__ __forceinline__ float sig_hw(float x) {
    return fmaf(0.5f, tanh_hw(0.5f * x), 0.5f);
}

// tf32 conversion (round-to-nearest)
__device__ __forceinline__ unsigned f2tf(float x) {
    unsigned r;
    asm("cvt.rna.tf32.f32 %0, %1;" : "=r"(r) : "f"(x));
    return r;
}

// m16n8k8 tf32 MMA
__device__ __forceinline__ void mma_tf32(float* c, const unsigned* a,
                                         unsigned b0, unsigned b1) {
    asm("mma.sync.aligned.m16n8k8.row.col.f32.tf32.tf32.f32 "
        "{%0,%1,%2,%3}, {%4,%5,%6,%7}, {%8,%9}, {%0,%1,%2,%3};"
        : "+f"(c[0]), "+f"(c[1]), "+f"(c[2]), "+f"(c[3])
        : "r"(a[0]), "r"(a[1]), "r"(a[2]), "r"(a[3]), "r"(b0), "r"(b1));
}

// named barriers (count must be multiple of 32)
__device__ __forceinline__ void bar_sync(int id, int cnt) {
    asm volatile("bar.sync %0, %1;" :: "r"(id), "r"(cnt) : "memory");
}
__device__ __forceinline__ void bar_arrive(int id, int cnt) {
    asm volatile("bar.arrive %0, %1;" :: "r"(id), "r"(cnt) : "memory");
}

// ---------------------------------------------------------------------------
// 0) reset stamp buffers (must run before each scan launch)
// ---------------------------------------------------------------------------
__global__ void init_stamps_kernel() {
    int i = blockIdx.x * blockDim.x + threadIdx.x;
    if (i < 2 * 2 * HD) g_hstamp[i] = 0ULL;
}

// ---------------------------------------------------------------------------
// 1) embedding gather: x0[t][e] = emb[sentence[t]][e]
// ---------------------------------------------------------------------------
__global__ void embed_kernel(const int* __restrict__ sentence,
                             const float* __restrict__ emb) {
    int t = blockIdx.x;
    int v = sentence[t];
    const float4* src = (const float4*)(emb + (size_t)v * EMB);
    float4* dst = (float4*)(g_x0 + (size_t)t * EMB);
    dst[threadIdx.x] = src[threadIdx.x];   // 128 threads * float4 = 512 floats
}

// ---------------------------------------------------------------------------
// 2) input-projection GEMM — tf32 tensor cores, 3-term split (hh + hl + lh),
//    hoisted conversions (R8) + SOFTWARE-PIPELINED global loads (new):
//    tile i+1's loads issue right after smem-ready sync, fly during compute.
// ---------------------------------------------------------------------------
#define BM 128
#define BN 128
#define BK 16
#define PAD 136   // smem row stride (words): conflict-free

__global__ void __launch_bounds__(256)
gemm_bias_kernel(const float* __restrict__ W,
                 const float* __restrict__ b1,
                 const float* __restrict__ b2,
                 int K, int layer) {
    const float* A = layer ? g_hcat0 : g_x0;
    __shared__ unsigned Ah[BK][PAD], Al[BK][PAD];
    __shared__ unsigned Bh[BK][PAD], Bl[BK][PAD];

    int dir = blockIdx.z;
    const float* Wd = W + (size_t)dir * G4H * K;
    float* Cd = g_G + (size_t)dir * TSEQ * G4H;

    int tid = threadIdx.x;
    int m0 = blockIdx.y * BM, n0 = blockIdx.x * BN;
    int w = tid >> 5, lane = tid & 31;
    int wm = w & 3, wn = w >> 2;     // 4 x 2 warp grid
    int g = lane >> 2, tig = lane & 3;
    int rb = wm * 32;                // warp row base in tile
    int cb = wn * 64;                // warp col base in tile

    float acc[2][8][4];
#pragma unroll
    for (int i = 0; i < 2; i++)
#pragma unroll
        for (int j = 0; j < 8; j++)
#pragma unroll
            for (int r = 0; r < 4; r++) acc[i][j][r] = 0.0f;

    int lr = tid >> 1;            // 0..127
    int lc = (tid & 1) * 8;       // 0 or 8

    const float* Arow = A  + (size_t)(m0 + lr) * K + lc;
    const float* Wrow = Wd + (size_t)(n0 + lr) * K + lc;

    // prologue: load tile 0
    float av[8], wv[8];
    *(float4*)(av)     = *(const float4*)(Arow);
    *(float4*)(av + 4) = *(const float4*)(Arow + 4);
    *(float4*)(wv)     = *(const float4*)(Wrow);
    *(float4*)(wv + 4) = *(const float4*)(Wrow + 4);

    for (int k0 = 0; k0 < K; k0 += BK) {
        __syncthreads();   // smem consumers of previous tile done
#pragma unroll
        for (int i = 0; i < 8; i++) {
            unsigned hi = f2tf(av[i]);
            Ah[lc + i][lr] = hi;
            Al[lc + i][lr] = f2tf(av[i] - __uint_as_float(hi));
            unsigned wh = f2tf(wv[i]);
            Bh[lc + i][lr] = wh;
            Bl[lc + i][lr] = f2tf(wv[i] - __uint_as_float(wh));
        }
        __syncthreads();   // smem tile ready

        // issue next tile's loads NOW; they fly during compute below
        if (k0 + BK < K) {
            const float* an = Arow + k0 + BK;
            const float* wn2 = Wrow + k0 + BK;
            *(float4*)(av)     = *(const float4*)(an);
            *(float4*)(av + 4) = *(const float4*)(an + 4);
            *(float4*)(wv)     = *(const float4*)(wn2);
            *(float4*)(wv + 4) = *(const float4*)(wn2 + 4);
        }

#pragma unroll
        for (int ks = 0; ks < BK; ks += 8) {
            unsigned ah[2][4], al[2][4];
#pragma unroll
            for (int mt = 0; mt < 2; mt++) {
                int r0 = rb + mt * 16 + g;
                ah[mt][0] = Ah[ks + tig][r0];
                ah[mt][1] = Ah[ks + tig][r0 + 8];
                ah[mt][2] = Ah[ks + tig + 4][r0];
                ah[mt][3] = Ah[ks + tig + 4][r0 + 8];
                al[mt][0] = Al[ks + tig][r0];
                al[mt][1] = Al[ks + tig][r0 + 8];
                al[mt][2] = Al[ks + tig + 4][r0];
                al[mt][3] = Al[ks + tig + 4][r0 + 8];
            }
#pragma unroll
            for (int nt = 0; nt < 8; nt++) {
                int n = cb + nt * 8 + g;
                unsigned bh0 = Bh[ks + tig][n];
                unsigned bh1 = Bh[ks + tig + 4][n];
                unsigned bl0 = Bl[ks + tig][n];
                unsigned bl1 = Bl[ks + tig + 4][n];
#pragma unroll
                for (int mt = 0; mt < 2; mt++) {
                    mma_tf32(acc[mt][nt], ah[mt], bh0, bh1);   // hi*hi
                    mma_tf32(acc[mt][nt], ah[mt], bl0, bl1);   // hi*lo
                    mma_tf32(acc[mt][nt], al[mt], bh0, bh1);   // lo*hi
                }
            }
        }
    }

    const float* b1d = b1 + (size_t)dir * G4H;
    const float* b2d = b2 + (size_t)dir * G4H;
#pragma unroll
    for (int nt = 0; nt < 8; nt++) {
        int n = n0 + cb + nt * 8 + 2 * tig;
        float bias0 = b1d[n]     + b2d[n];
        float bias1 = b1d[n + 1] + b2d[n + 1];
#pragma unroll
        for (int mt = 0; mt < 2; mt++) {
            int row = m0 + rb + mt * 16 + g;
            float2 v0, v1;
            v0.x = acc[mt][nt][0] + bias0;
            v0.y = acc[mt][nt][1] + bias1;
            v1.x = acc[mt][nt][2] + bias0;
            v1.y = acc[mt][nt][3] + bias1;
            *(float2*)(Cd + (size_t)row * G4H + n)       = v0;
            *(float2*)(Cd + (size_t)(row + 8) * G4H + n) = v1;
        }
    }
}

// ---------------------------------------------------------------------------
// 3) recurrent scan — R9 warp-specialized protocol, FROZEN, with one free
//    reorder: seg7 stages gin (register-resident) BEFORE the poll, taking it
//    off the post-dot arrive path. 8 producer warps + 1 cell warp,
//    parity-split named barriers.
// ---------------------------------------------------------------------------
#define SCAN_THREADS 288   // 9 warps

__global__ void __launch_bounds__(SCAN_THREADS, 1)
scan_kernel(const float* __restrict__ Whh, int layer) {
    float* hcat = layer ? g_hcat1 : g_hcat0;
    const int dir  = blockIdx.x >> 6;
    const int cta  = blockIdx.x & 63;
    const int j0   = cta * 8;
    const int tid  = threadIdx.x;
    const int w    = tid >> 5;       // 0 = cell warp; 1..8 = producers
    const int lane = tid & 31;

    __shared__ __align__(16) float hbuf[8][64];
    __shared__ float part[2][8][32];
    __shared__ float gin[2][32];

    const float* Gd = g_G + (size_t)dir * TSEQ * G4H;
    unsigned long long* stampBase = g_hstamp + (size_t)dir * 2 * HD;

    if (w == 0) {
        // ---------------- cell warp ----------------
        float creg = 0.0f;   // cell state for unit j0+lane (lanes 0..7)
        for (int s = 0; s < TSEQ; s++) {
            const int t   = dir ? (TSEQ - 1 - s) : s;
            const int par = s & 1;
            bar_sync(1 + par, SCAN_THREADS);   // parts + gin for step s ready

            float g = gin[par][lane];
#pragma unroll
            for (int p = 0; p < 8; p++) g += part[par][p][lane];
            float fg = __shfl_down_sync(0xffffffffu, g, 8);
            float gg = __shfl_down_sync(0xffffffffu, g, 16);
            float og = __shfl_down_sync(0xffffffffu, g, 24);
            if (lane < 8) {
                float c = sig_hw(fg) * creg + sig_hw(g) * tanh_hw(gg);
                creg = c;
                float h = sig_hw(og) * tanh_hw(c);
                // publish FIRST (unblocks all consumer CTAs), then persist
                unsigned long long pk =
                    ((unsigned long long)(unsigned)(s + 1) << 32) |
                    (unsigned long long)__float_as_uint(h);
                st_relaxed_u64(stampBase + (size_t)par * HD + j0 + lane, pk);
                hcat[(size_t)t * (2 * HD) + dir * HD + j0 + lane] = h;
            }
        }
    } else {
        // ---------------- producer warps ----------------
        const int seg = w - 1;               // k-segment 0..7
        const int row = lane;                // gate-row 0..31
        const int q = row >> 3, jj = row & 7;
        const int R = q * HD + j0 + jj;      // global gate row in [0,4H)

        // Whh slice in registers as packed pairs: 64 floats = 32 u64
        const ulonglong2* wsrc2 =
            (const ulonglong2*)(Whh + ((size_t)dir * G4H + R) * HD + seg * 64);
        ulonglong2 w2[16];
#pragma unroll
        for (int i = 0; i < 16; i++) w2[i] = wsrc2[i];

        // seg7 warp stages G rows (prefetch one step ahead)
        float gnext = 0.0f;
        if (seg == 7) {
            int t0 = dir ? (TSEQ - 1) : 0;
            gnext = __ldg(Gd + (size_t)t0 * G4H + R);
        }

        for (int s = 0; s < TSEQ; s++) {
            const int par = s & 1;

            // seg7: stage this step's G early (register-resident; only read
            // by cell warp after all arrives), prefetch next
            if (seg == 7) {
                gin[par][row] = gnext;
                if (s + 1 < TSEQ) {
                    int tn = dir ? (TSEQ - 2 - s) : (s + 1);
                    gnext = __ldg(Gd + (size_t)tn * G4H + R);
                }
            }

            // fill this warp's 64-float h segment
            if (s == 0) {
                hbuf[seg][lane * 2]     = 0.0f;
                hbuf[seg][lane * 2 + 1] = 0.0f;
            } else {
                const unsigned long long* src =
                    stampBase + ((size_t)((s + 1) & 1)) * HD + seg * 64 + lane * 2;
                const unsigned need = (unsigned)s;
                unsigned long long v0, v1;
                for (;;) {
                    v0 = ld_relaxed_u64(src);
                    v1 = ld_relaxed_u64(src + 1);
                    bool ok = ((unsigned)(v0 >> 32) >= need) &&
                              ((unsigned)(v1 >> 32) >= need);
                    if (__all_sync(0xffffffffu, ok)) break;
                }
                hbuf[seg][lane * 2]     = __uint_as_float((unsigned)v0);
                hbuf[seg][lane * 2 + 1] = __uint_as_float((unsigned)v1);
            }
            __syncwarp();

            // packed dot: 32 FFMA2 (64 MACs) registers x smem-broadcast h
            const ulonglong2* hb2 = (const ulonglong2*)hbuf[seg];
            unsigned long long a0 = 0ULL, a1 = 0ULL, a2 = 0ULL, a3 = 0ULL;
#pragma unroll
            for (int i = 0; i < 16; i += 2) {
                ulonglong2 h0 = hb2[i];
                ulonglong2 h1 = hb2[i + 1];
                a0 = ffma2(w2[i].x,     h0.x, a0);
                a1 = ffma2(w2[i].y,     h0.y, a1);
                a2 = ffma2(w2[i + 1].x, h1.x, a2);
                a3 = ffma2(w2[i + 1].y, h1.y, a3);
            }
            float2 f0 = unpack2(a0), f1 = unpack2(a1),
                   f2 = unpack2(a2), f3 = unpack2(a3);
            part[par][seg][row] =
                ((f0.x + f0.y) + (f1.x + f1.y)) + ((f2.x + f2.y) + (f3.x + f3.y));

            bar_arrive(1 + par, SCAN_THREADS);   // step-s inputs ready for cell warp
        }
    }
}

// ---------------------------------------------------------------------------
// 4) tag projection: feats[t][tag] = hcat1[t] . W_tag[tag] + b_tag[tag]
// ---------------------------------------------------------------------------
__global__ void feats_kernel(const float* __restrict__ Wtag,
                             const float* __restrict__ btag) {
    int t = blockIdx.x;
    __shared__ float xs[2 * HD];
    for (int i = threadIdx.x; i < 2 * HD; i += 192)
        xs[i] = g_hcat1[(size_t)t * (2 * HD) + i];
    __syncthreads();
    int tag = threadIdx.x / 16;
    int sg  = threadIdx.x % 16;
    const float* w = Wtag + (size_t)tag * (2 * HD) + sg * 64;
    const float* x = xs + sg * 64;
    float s = 0.0f;
#pragma unroll
    for (int i = 0; i < 64; i++) s = fmaf(w[i], x[i], s);
#pragma unroll
    for (int o = 8; o > 0; o >>= 1)
        s += __shfl_down_sync(0xffffffffu, s, o, 16);
    if (sg == 0) g_feats[t * NTAGS + tag] = s + btag[tag];
}

// ---------------------------------------------------------------------------
// 5) Viterbi + backtrace (single block; warp0 scans; feats staged in smem)
// ---------------------------------------------------------------------------
#define VIT_SMEM (TSEQ * NTAGS * 4 + TSEQ * NTAGS)

__global__ void viterbi_kernel(const float* __restrict__ trans,
                               float* __restrict__ out, int out_size) {
    extern __shared__ char vsm[];
    float* fsh = (float*)vsm;
    unsigned char* bp = (unsigned char*)(vsm + TSEQ * NTAGS * 4);

    for (int i = threadIdx.x; i < TSEQ * NTAGS; i += blockDim.x)
        fsh[i] = g_feats[i];
    __syncthreads();

    if (threadIdx.x >= 32) return;
    const int lane = threadIdx.x;

    float tr[NTAGS];
    if (lane < NTAGS) {
#pragma unroll
        for (int p = 0; p < NTAGS; p++) tr[p] = trans[lane * NTAGS + p];
    } else {
#pragma unroll
        for (int p = 0; p < NTAGS; p++) tr[p] = -3e38f;
    }

    float fv = (lane == START_TAG) ? 0.0f : ((lane < NTAGS) ? NEGV : -3e38f);
    float featp = (lane < NTAGS) ? fsh[lane] : 0.0f;

    for (int t = 0; t < TSEQ; t++) {
        float featn = (lane < NTAGS && t + 1 < TSEQ) ? fsh[(t + 1) * NTAGS + lane] : 0.0f;
        float best = -3e38f;
        int arg = 0;
#pragma unroll
        for (int p = 0; p < NTAGS; p++) {
            float fp = __shfl_sync(0xffffffffu, fv, p);
            float sc = fp + tr[p];
            if (sc > best) { best = sc; arg = p; }
        }
        if (lane < NTAGS) {
            bp[t * NTAGS + lane] = (unsigned char)arg;
            fv = best + featp;
        } else {
            fv = -3e38f;
        }
        featp = featn;
    }

    float term = (lane < NTAGS) ? fv + trans[STOP_TAG * NTAGS + lane] : -3e38f;
    float bs = term;
    int bi = lane;
#pragma unroll
    for (int o = 16; o > 0; o >>= 1) {
        float os = __shfl_down_sync(0xffffffffu, bs, o);
        int   oi = __shfl_down_sync(0xffffffffu, bi, o);
        if (os > bs || (os == bs && oi < bi)) { bs = os; bi = oi; }
    }
    __syncwarp();

    if (lane == 0) {
        float score = bs;
        int tag = bi;
        if (out_size >= TSEQ + 1) {
            out[0] = score;
            out[TSEQ] = (float)tag;
            for (int t = TSEQ - 1; t >= 1; t--) {
                tag = bp[t * NTAGS + tag];
                out[t] = (float)tag;
            }
            for (int i = TSEQ + 1; i < out_size; i++) out[i] = 0.0f;
        } else {
            int n = out_size;
            if (n > 0) {
                if (TSEQ - 1 < n) out[TSEQ - 1] = (float)tag;
                for (int t = TSEQ - 1; t >= 1; t--) {
                    tag = bp[t * NTAGS + tag];
                    if (t - 1 < n) out[t - 1] = (float)tag;
                }
            }
        }
    }
}

// ---------------------------------------------------------------------------
// launch
// ---------------------------------------------------------------------------
extern "C" void kernel_launch(void* const* d_in, const int* in_sizes, int n_in,
                              void* d_out, int out_size) {
    const int*   sentence = (const int*)  d_in[0];
    const float* emb      = (const float*)d_in[1];
    const float* Wih0     = (const float*)d_in[2];
    const float* Whh0     = (const float*)d_in[3];
    const float* bih0     = (const float*)d_in[4];
    const float* bhh0     = (const float*)d_in[5];
    const float* Wih1     = (const float*)d_in[6];
    const float* Whh1     = (const float*)d_in[7];
    const float* bih1     = (const float*)d_in[8];
    const float* bhh1     = (const float*)d_in[9];
    const float* Wtag     = (const float*)d_in[10];
    const float* btag     = (const float*)d_in[11];
    const float* trans    = (const float*)d_in[12];
    float* out = (float*)d_out;

    cudaFuncSetAttribute(viterbi_kernel,
                         cudaFuncAttributeMaxDynamicSharedMemorySize, VIT_SMEM);

    embed_kernel<<<TSEQ, 128>>>(sentence, emb);

    // ---- layer 0 ----
    init_stamps_kernel<<<4, 512>>>();
    gemm_bias_kernel<<<dim3(16, 16, 2), 256>>>(Wih0, bih0, bhh0, EMB, 0);
    scan_kernel<<<128, SCAN_THREADS>>>(Whh0, 0);

    // ---- layer 1 ----
    init_stamps_kernel<<<4, 512>>>();
    gemm_bias_kernel<<<dim3(16, 16, 2), 256>>>(Wih1, bih1, bhh1, 2 * HD, 1);
    scan_kernel<<<128, SCAN_THREADS>>>(Whh1, 1);

    // ---- CRF ----
    feats_kernel<<<TSEQ, 192>>>(Wtag, btag);
    viterbi_kernel<<<1, 128, VIT_SMEM>>>(trans, out, out_size);
}

// round 11
// speedup vs baseline: 1.0288x; 1.0288x over previous
#include <cuda_runtime.h>
#include <cuda_bf16.h>
#include <math.h>

// ---------------------------------------------------------------------------
// Problem constants
// ---------------------------------------------------------------------------
#define TSEQ 2048
#define HD   512        // hidden size H
#define EMB  512        // embedding dim E
#define G4H  2048       // 4*H
#define NTAGS 12
#define START_TAG 10
#define STOP_TAG  11
#define NEGV (-10000.0f)

// ---------------------------------------------------------------------------
// Scratch (device globals; no allocations allowed)
// ---------------------------------------------------------------------------
__device__ float g_x0[TSEQ * EMB];                 // embedded input      4 MB
__device__ float g_G[2 * TSEQ * G4H];              // input projections  32 MB (reused per layer)
__device__ float g_hcat0[TSEQ * 2 * HD];           // layer0 output       8 MB
__device__ float g_hcat1[TSEQ * 2 * HD];           // layer1 output       8 MB
__device__ float g_feats[TSEQ * NTAGS];
__device__ unsigned long long g_hstamp[2 * 2 * HD]; // [dir][parity][H] stamped h
__device__ int g_ticket;                            // GEMM tile ticket
__device__ int g_ready[2][32];                      // per (dir, mtile) done count

// ---------------------------------------------------------------------------
// Helpers
// ---------------------------------------------------------------------------
__device__ __forceinline__ unsigned long long ld_relaxed_u64(const unsigned long long* p) {
    unsigned long long v;
    asm volatile("ld.relaxed.gpu.global.b64 %0, [%1];" : "=l"(v) : "l"(p) : "memory");
    return v;
}
__device__ __forceinline__ void st_relaxed_u64(unsigned long long* p, unsigned long long v) {
    asm volatile("st.relaxed.gpu.global.b64 [%0], %1;" :: "l"(p), "l"(v) : "memory");
}
__device__ __forceinline__ int ld_acquire_s32(const int* p) {
    int v;
    asm volatile("ld.acquire.gpu.global.s32 %0, [%1];" : "=r"(v) : "l"(p) : "memory");
    return v;
}

// packed f32x2 FMA (FFMA2 — only reachable via PTX)
__device__ __forceinline__ unsigned long long ffma2(unsigned long long a,
                                                    unsigned long long b,
                                                    unsigned long long c) {
    unsigned long long d;
    asm("fma.rn.f32x2 %0, %1, %2, %3;" : "=l"(d) : "l"(a), "l"(b), "l"(c));
    return d;
}
__device__ __forceinline__ float2 unpack2(unsigned long long v) {
    float2 r;
    asm("mov.b64 {%0, %1}, %2;" : "=f"(r.x), "=f"(r.y) : "l"(v));
    return r;
}

// HW tanh (MUFU-class, ~1e-5 abs err) and sigmoid via tanh
__device__ __forceinline__ float tanh_hw(float x) {
    float y;
    asm("tanh.approx.f32 %0, %1;" : "=f"(y) : "f"(x));
    return y;
}
__device__ __forceinline__ float sig_hw(float x) {
    return fmaf(0.5f, tanh_hw(0.5f * x), 0.5f);
}

// tf32 conversion (round-to-nearest)
__device__ __forceinline__ unsigned f2tf(float x) {
    unsigned r;
    asm("cvt.rna.tf32.f32 %0, %1;" : "=r"(r) : "f"(x));
    return r;
}

// m16n8k8 tf32 MMA
__device__ __forceinline__ void mma_tf32(float* c, const unsigned* a,
                                         unsigned b0, unsigned b1) {
    asm("mma.sync.aligned.m16n8k8.row.col.f32.tf32.tf32.f32 "
        "{%0,%1,%2,%3}, {%4,%5,%6,%7}, {%8,%9}, {%0,%1,%2,%3};"
        : "+f"(c[0]), "+f"(c[1]), "+f"(c[2]), "+f"(c[3])
        : "r"(a[0]), "r"(a[1]), "r"(a[2]), "r"(a[3]), "r"(b0), "r"(b1));
}

// named barriers (count must be multiple of 32)
__device__ __forceinline__ void bar_sync(int id, int cnt) {
    asm volatile("bar.sync %0, %1;" :: "r"(id), "r"(cnt) : "memory");
}
__device__ __forceinline__ void bar_arrive(int id, int cnt) {
    asm volatile("bar.arrive %0, %1;" :: "r"(id), "r"(cnt) : "memory");
}

// ---------------------------------------------------------------------------
// 0) reset stamp buffers + GEMM tickets/counters (before each fused launch)
// ---------------------------------------------------------------------------
__global__ void init_stamps_kernel() {
    int i = blockIdx.x * blockDim.x + threadIdx.x;
    if (i < 2 * 2 * HD) g_hstamp[i] = 0ULL;
    if (i == 0) g_ticket = 0;
    if (i < 64) ((int*)g_ready)[i] = 0;
}

// ---------------------------------------------------------------------------
// 1) embedding gather: x0[t][e] = emb[sentence[t]][e]
// ---------------------------------------------------------------------------
__global__ void embed_kernel(const int* __restrict__ sentence,
                             const float* __restrict__ emb) {
    int t = blockIdx.x;
    int v = sentence[t];
    const float4* src = (const float4*)(emb + (size_t)v * EMB);
    float4* dst = (float4*)(g_x0 + (size_t)t * EMB);
    dst[threadIdx.x] = src[threadIdx.x];   // 128 threads * float4 = 512 floats
}

// ---------------------------------------------------------------------------
// 2) FUSED scan + background GEMM.
//    128 CTAs x 416 threads (13 warps):
//      wid 0..3  : GEMM warps — pull 64x128 tiles by global ticket, compute the
//                  input projection (3-term tf32 split, proven R8 math) into
//                  g_G, signal g_ready[dir][mtile]. Never wait on scan.
//      wid 4..11 : scan producer warps (seg 0..7) — R9 protocol, frozen.
//      wid 12    : cell warp — R9 protocol, frozen (highest wid = arbiter prio).
//    Ticket order interleaves (dir0, mtile ascending) with (dir1, mtile
//    descending) to match scan consumption. seg7 polls g_ready (acquire)
//    once per 64-step group before prefetching G.
// ---------------------------------------------------------------------------
#define FUSED_THREADS 416
#define SCAN_CNT 288          // 9 scan warps on barriers 1,2
#define GEMM_CNT 128          // 4 gemm warps on barrier 3
#define NTILES_TOTAL 1024     // 32 mtiles * 16 ntiles * 2 dirs

__global__ void __launch_bounds__(FUSED_THREADS, 1)
scan_gemm_kernel(const float* __restrict__ Whh,
                 const float* __restrict__ Wih,
                 const float* __restrict__ b1,
                 const float* __restrict__ b2,
                 int layer) {
    __shared__ unsigned Ah[16][72], Al[16][72];
    __shared__ unsigned Bh[16][136], Bl[16][136];
    __shared__ __align__(16) float hbuf[8][64];
    __shared__ float part[2][8][32];
    __shared__ float gin[2][32];
    __shared__ int s_ticket;

    const int K = layer ? (2 * HD) : EMB;
    const float* Asrc = layer ? g_hcat0 : g_x0;
    float* hcat = layer ? g_hcat1 : g_hcat0;

    const int dir = blockIdx.x >> 6;
    const int cta = blockIdx.x & 63;
    const int j0  = cta * 8;
    const int tid = threadIdx.x;
    const int w   = tid >> 5;
    const int lane = tid & 31;

    unsigned long long* stampBase = g_hstamp + (size_t)dir * 2 * HD;
    const float* Gd = g_G + (size_t)dir * TSEQ * G4H;

    if (w < 4) {
        // ================= GEMM warps =================
        const int g = lane >> 2, tig = lane & 3;
        const int lr = tid >> 1;          // 0..63  (A tile row)
        const int lc = (tid & 1) * 8;     // 0 or 8 (A tile k-half)

        for (;;) {
            if (tid == 0) s_ticket = atomicAdd(&g_ticket, 1);
            bar_sync(3, GEMM_CNT);
            int tk = s_ticket;
            if (tk >= NTILES_TOTAL) break;

            int gg = tk >> 5;
            int r = tk & 31;
            int tdir = r >> 4;
            int ntile = r & 15;
            int mtile = tdir ? (31 - gg) : gg;

            const float* Wd = Wih + (size_t)tdir * G4H * K;
            const float* b1d = b1 + (size_t)tdir * G4H;
            const float* b2d = b2 + (size_t)tdir * G4H;
            float* Cd = g_G + (size_t)tdir * TSEQ * G4H;

            float acc[16][4];
#pragma unroll
            for (int nt = 0; nt < 16; nt++)
#pragma unroll
                for (int q = 0; q < 4; q++) acc[nt][q] = 0.0f;

            const float* Arow = Asrc + (size_t)(mtile * 64 + lr) * K + lc;
            const float* Wrow = Wd + (size_t)(ntile * 128 + tid) * K;

            for (int k0 = 0; k0 < K; k0 += 16) {
                float av[8], wv[16];
                *(float4*)(av)      = *(const float4*)(Arow + k0);
                *(float4*)(av + 4)  = *(const float4*)(Arow + k0 + 4);
                *(float4*)(wv)      = *(const float4*)(Wrow + k0);
                *(float4*)(wv + 4)  = *(const float4*)(Wrow + k0 + 4);
                *(float4*)(wv + 8)  = *(const float4*)(Wrow + k0 + 8);
                *(float4*)(wv + 12) = *(const float4*)(Wrow + k0 + 12);
                bar_sync(3, GEMM_CNT);      // prev tile-slice consumers done
#pragma unroll
                for (int i = 0; i < 8; i++) {
                    unsigned hi = f2tf(av[i]);
                    Ah[lc + i][lr] = hi;
                    Al[lc + i][lr] = f2tf(av[i] - __uint_as_float(hi));
                }
#pragma unroll
                for (int j = 0; j < 16; j++) {
                    unsigned wh = f2tf(wv[j]);
                    Bh[j][tid] = wh;
                    Bl[j][tid] = f2tf(wv[j] - __uint_as_float(wh));
                }
                bar_sync(3, GEMM_CNT);      // smem tile ready

#pragma unroll
                for (int ks = 0; ks < 16; ks += 8) {
                    unsigned ah[4], al[4];
                    int r0 = w * 16 + g;
                    ah[0] = Ah[ks + tig][r0];
                    ah[1] = Ah[ks + tig][r0 + 8];
                    ah[2] = Ah[ks + tig + 4][r0];
                    ah[3] = Ah[ks + tig + 4][r0 + 8];
                    al[0] = Al[ks + tig][r0];
                    al[1] = Al[ks + tig][r0 + 8];
                    al[2] = Al[ks + tig + 4][r0];
                    al[3] = Al[ks + tig + 4][r0 + 8];
#pragma unroll
                    for (int nt = 0; nt < 16; nt++) {
                        int n = nt * 8 + g;
                        unsigned bh0 = Bh[ks + tig][n];
                        unsigned bh1 = Bh[ks + tig + 4][n];
                        unsigned bl0 = Bl[ks + tig][n];
                        unsigned bl1 = Bl[ks + tig + 4][n];
                        mma_tf32(acc[nt], ah, bh0, bh1);   // hi*hi
                        mma_tf32(acc[nt], ah, bl0, bl1);   // hi*lo
                        mma_tf32(acc[nt], al, bh0, bh1);   // lo*hi
                    }
                }
            }

            // epilogue: bias + store
            int row = mtile * 64 + w * 16 + g;
#pragma unroll
            for (int nt = 0; nt < 16; nt++) {
                int n = ntile * 128 + nt * 8 + 2 * tig;
                float bias0 = b1d[n] + b2d[n];
                float bias1 = b1d[n + 1] + b2d[n + 1];
                float2 v0, v1;
                v0.x = acc[nt][0] + bias0; v0.y = acc[nt][1] + bias1;
                v1.x = acc[nt][2] + bias0; v1.y = acc[nt][3] + bias1;
                *(float2*)(Cd + (size_t)row * G4H + n)       = v0;
                *(float2*)(Cd + (size_t)(row + 8) * G4H + n) = v1;
            }
            __threadfence();                // my stores visible GPU-wide
            bar_sync(3, GEMM_CNT);          // all 128 threads' stores fenced
            if (tid == 0) atomicAdd(&g_ready[tdir][mtile], 1);
        }
        return;   // GEMM warps exit; scan barriers (1,2 cnt 288) unaffected
    }

    if (w == 12) {
        // ================= cell warp (R9 frozen) =================
        float creg = 0.0f;
        for (int s = 0; s < TSEQ; s++) {
            const int t   = dir ? (TSEQ - 1 - s) : s;
            const int par = s & 1;
            bar_sync(1 + par, SCAN_CNT);

            float g = gin[par][lane];
#pragma unroll
            for (int p = 0; p < 8; p++) g += part[par][p][lane];
            float fg = __shfl_down_sync(0xffffffffu, g, 8);
            float gg = __shfl_down_sync(0xffffffffu, g, 16);
            float og = __shfl_down_sync(0xffffffffu, g, 24);
            if (lane < 8) {
                float c = sig_hw(fg) * creg + sig_hw(g) * tanh_hw(gg);
                creg = c;
                float h = sig_hw(og) * tanh_hw(c);
                unsigned long long pk =
                    ((unsigned long long)(unsigned)(s + 1) << 32) |
                    (unsigned long long)__float_as_uint(h);
                st_relaxed_u64(stampBase + (size_t)par * HD + j0 + lane, pk);
                hcat[(size_t)t * (2 * HD) + dir * HD + j0 + lane] = h;
            }
        }
    } else {
        // ================= producer warps (R9 frozen + G ready-poll) ======
        const int seg = w - 4;               // k-segment 0..7
        const int row = lane;                // gate-row 0..31
        const int q = row >> 3, jj = row & 7;
        const int R = q * HD + j0 + jj;

        const ulonglong2* wsrc2 =
            (const ulonglong2*)(Whh + ((size_t)dir * G4H + R) * HD + seg * 64);
        ulonglong2 w2[16];
#pragma unroll
        for (int i = 0; i < 16; i++) w2[i] = wsrc2[i];

        float gnext = 0.0f;
        int lastGrp = -1;
        if (seg == 7) {
            int t0 = dir ? (TSEQ - 1) : 0;
            int grp = t0 >> 6;
            while (ld_acquire_s32(&g_ready[dir][grp]) < 16) {}
            lastGrp = grp;
            gnext = __ldg(Gd + (size_t)t0 * G4H + R);
        }

        for (int s = 0; s < TSEQ; s++) {
            const int par = s & 1;

            // fill this warp's 64-float h segment
            if (s == 0) {
                hbuf[seg][lane * 2]     = 0.0f;
                hbuf[seg][lane * 2 + 1] = 0.0f;
            } else {
                const unsigned long long* src =
                    stampBase + ((size_t)((s + 1) & 1)) * HD + seg * 64 + lane * 2;
                const unsigned need = (unsigned)s;
                unsigned long long v0, v1;
                for (;;) {
                    v0 = ld_relaxed_u64(src);
                    v1 = ld_relaxed_u64(src + 1);
                    bool ok = ((unsigned)(v0 >> 32) >= need) &&
                              ((unsigned)(v1 >> 32) >= need);
                    if (__all_sync(0xffffffffu, ok)) break;
                }
                hbuf[seg][lane * 2]     = __uint_as_float((unsigned)v0);
                hbuf[seg][lane * 2 + 1] = __uint_as_float((unsigned)v1);
            }
            __syncwarp();

            // packed dot: 32 FFMA2 (64 MACs)
            const ulonglong2* hb2 = (const ulonglong2*)hbuf[seg];
            unsigned long long a0 = 0ULL, a1 = 0ULL, a2 = 0ULL, a3 = 0ULL;
#pragma unroll
            for (int i = 0; i < 16; i += 2) {
                ulonglong2 h0 = hb2[i];
                ulonglong2 h1 = hb2[i + 1];
                a0 = ffma2(w2[i].x,     h0.x, a0);
                a1 = ffma2(w2[i].y,     h0.y, a1);
                a2 = ffma2(w2[i + 1].x, h1.x, a2);
                a3 = ffma2(w2[i + 1].y, h1.y, a3);
            }
            float2 f0 = unpack2(a0), f1 = unpack2(a1),
                   f2 = unpack2(a2), f3 = unpack2(a3);
            part[par][seg][row] =
                ((f0.x + f0.y) + (f1.x + f1.y)) + ((f2.x + f2.y) + (f3.x + f3.y));

            // seg7: stage this step's G, prefetch next (with ready-poll)
            if (seg == 7) {
                gin[par][row] = gnext;
                if (s + 1 < TSEQ) {
                    int tn = dir ? (TSEQ - 2 - s) : (s + 1);
                    int grp = tn >> 6;
                    if (grp != lastGrp) {
                        while (ld_acquire_s32(&g_ready[dir][grp]) < 16) {}
                        lastGrp = grp;
                    }
                    gnext = __ldg(Gd + (size_t)tn * G4H + R);
                }
            }

            bar_arrive(1 + par, SCAN_CNT);
        }
    }
}

// ---------------------------------------------------------------------------
// 4) tag projection: feats[t][tag] = hcat1[t] . W_tag[tag] + b_tag[tag]
// ---------------------------------------------------------------------------
__global__ void feats_kernel(const float* __restrict__ Wtag,
                             const float* __restrict__ btag) {
    int t = blockIdx.x;
    __shared__ float xs[2 * HD];
    for (int i = threadIdx.x; i < 2 * HD; i += 192)
        xs[i] = g_hcat1[(size_t)t * (2 * HD) + i];
    __syncthreads();
    int tag = threadIdx.x / 16;
    int sg  = threadIdx.x % 16;
    const float* w = Wtag + (size_t)tag * (2 * HD) + sg * 64;
    const float* x = xs + sg * 64;
    float s = 0.0f;
#pragma unroll
    for (int i = 0; i < 64; i++) s = fmaf(w[i], x[i], s);
#pragma unroll
    for (int o = 8; o > 0; o >>= 1)
        s += __shfl_down_sync(0xffffffffu, s, o, 16);
    if (sg == 0) g_feats[t * NTAGS + tag] = s + btag[tag];
}

// ---------------------------------------------------------------------------
// 5) Viterbi + backtrace (single block; warp0 scans; feats staged in smem)
// ---------------------------------------------------------------------------
#define VIT_SMEM (TSEQ * NTAGS * 4 + TSEQ * NTAGS)

__global__ void viterbi_kernel(const float* __restrict__ trans,
                               float* __restrict__ out, int out_size) {
    extern __shared__ char vsm[];
    float* fsh = (float*)vsm;
    unsigned char* bp = (unsigned char*)(vsm + TSEQ * NTAGS * 4);

    for (int i = threadIdx.x; i < TSEQ * NTAGS; i += blockDim.x)
        fsh[i] = g_feats[i];
    __syncthreads();

    if (threadIdx.x >= 32) return;
    const int lane = threadIdx.x;

    float tr[NTAGS];
    if (lane < NTAGS) {
#pragma unroll
        for (int p = 0; p < NTAGS; p++) tr[p] = trans[lane * NTAGS + p];
    } else {
#pragma unroll
        for (int p = 0; p < NTAGS; p++) tr[p] = -3e38f;
    }

    float fv = (lane == START_TAG) ? 0.0f : ((lane < NTAGS) ? NEGV : -3e38f);
    float featp = (lane < NTAGS) ? fsh[lane] : 0.0f;

    for (int t = 0; t < TSEQ; t++) {
        float featn = (lane < NTAGS && t + 1 < TSEQ) ? fsh[(t + 1) * NTAGS + lane] : 0.0f;
        float best = -3e38f;
        int arg = 0;
#pragma unroll
        for (int p = 0; p < NTAGS; p++) {
            float fp = __shfl_sync(0xffffffffu, fv, p);
            float sc = fp + tr[p];
            if (sc > best) { best = sc; arg = p; }
        }
        if (lane < NTAGS) {
            bp[t * NTAGS + lane] = (unsigned char)arg;
            fv = best + featp;
        } else {
            fv = -3e38f;
        }
        featp = featn;
    }

    float term = (lane < NTAGS) ? fv + trans[STOP_TAG * NTAGS + lane] : -3e38f;
    float bs = term;
    int bi = lane;
#pragma unroll
    for (int o = 16; o > 0; o >>= 1) {
        float os = __shfl_down_sync(0xffffffffu, bs, o);
        int   oi = __shfl_down_sync(0xffffffffu, bi, o);
        if (os > bs || (os == bs && oi < bi)) { bs = os; bi = oi; }
    }
    __syncwarp();

    if (lane == 0) {
        float score = bs;
        int tag = bi;
        if (out_size >= TSEQ + 1) {
            out[0] = score;
            out[TSEQ] = (float)tag;
            for (int t = TSEQ - 1; t >= 1; t--) {
                tag = bp[t * NTAGS + tag];
                out[t] = (float)tag;
            }
            for (int i = TSEQ + 1; i < out_size; i++) out[i] = 0.0f;
        } else {
            int n = out_size;
            if (n > 0) {
                if (TSEQ - 1 < n) out[TSEQ - 1] = (float)tag;
                for (int t = TSEQ - 1; t >= 1; t--) {
                    tag = bp[t * NTAGS + tag];
                    if (t - 1 < n) out[t - 1] = (float)tag;
                }
            }
        }
    }
}

// ---------------------------------------------------------------------------
// launch
// ---------------------------------------------------------------------------
extern "C" void kernel_launch(void* const* d_in, const int* in_sizes, int n_in,
                              void* d_out, int out_size) {
    const int*   sentence = (const int*)  d_in[0];
    const float* emb      = (const float*)d_in[1];
    const float* Wih0     = (const float*)d_in[2];
    const float* Whh0     = (const float*)d_in[3];
    const float* bih0     = (const float*)d_in[4];
    const float* bhh0     = (const float*)d_in[5];
    const float* Wih1     = (const float*)d_in[6];
    const float* Whh1     = (const float*)d_in[7];
    const float* bih1     = (const float*)d_in[8];
    const float* bhh1     = (const float*)d_in[9];
    const float* Wtag     = (const float*)d_in[10];
    const float* btag     = (const float*)d_in[11];
    const float* trans    = (const float*)d_in[12];
    float* out = (float*)d_out;

    cudaFuncSetAttribute(viterbi_kernel,
                         cudaFuncAttributeMaxDynamicSharedMemorySize, VIT_SMEM);

    embed_kernel<<<TSEQ, 128>>>(sentence, emb);

    // ---- layer 0 (fused GEMM + scan) ----
    init_stamps_kernel<<<4, 512>>>();
    scan_gemm_kernel<<<128, FUSED_THREADS>>>(Whh0, Wih0, bih0, bhh0, 0);

    // ---- layer 1 (fused GEMM + scan) ----
    init_stamps_kernel<<<4, 512>>>();
    scan_gemm_kernel<<<128, FUSED_THREADS>>>(Whh1, Wih1, bih1, bhh1, 1);

    // ---- CRF ----
    feats_kernel<<<TSEQ, 192>>>(Wtag, btag);
    viterbi_kernel<<<1, 128, VIT_SMEM>>>(trans, out, out_size);
}